// round 15
// baseline (speedup 1.0000x reference)
#include <cuda_runtime.h>
#include <cstdint>

#define E 128
#define L 64
#define MAX_B 8192
#define SROWS 32
#define MAX_PARTS (MAX_B / SROWS)
#define W0PAD 130

typedef unsigned long long ull;

__device__ __align__(16) float g_feats[3ull * MAX_B * E];
__device__ __align__(16) float g_part[3 * MAX_PARTS];

__device__ __forceinline__ float warp_sum32(float v) {
#pragma unroll
    for (int o = 16; o > 0; o >>= 1) v += __shfl_xor_sync(0xffffffffu, v, o);
    return v;
}

// ---- Blackwell packed f32x2 ops (SASS FFMA2/FADD2, PTX-only) ----
__device__ __forceinline__ ull fma2(ull a, ull b, ull c) {
    ull r; asm("fma.rn.f32x2 %0, %1, %2, %3;" : "=l"(r) : "l"(a), "l"(b), "l"(c));
    return r;
}
__device__ __forceinline__ ull add2(ull a, ull b) {
    ull r; asm("add.rn.f32x2 %0, %1, %2;" : "=l"(r) : "l"(a), "l"(b));
    return r;
}
__device__ __forceinline__ ull mul2(ull a, ull b) {
    ull r; asm("mul.rn.f32x2 %0, %1, %2;" : "=l"(r) : "l"(a), "l"(b));
    return r;
}
__device__ __forceinline__ float2 unpack2(ull v) {
    float2 f; asm("mov.b64 {%0, %1}, %2;" : "=f"(f.x), "=f"(f.y) : "l"(v));
    return f;
}
__device__ __forceinline__ ull pack2(float a, float b) {
    ull r; asm("mov.b64 %0, {%1, %2};" : "=l"(r) : "f"(a), "f"(b));
    return r;
}

// ---------------------------------------------------------------------------
// Fused branch kernel (R11 proven config): grid (B, 3), 256 threads,
// 8 rows/warp, packed f32x2 math, pairing tree, one exp per lane,
// unstabilized softmax. Only change: 32-bit byte-offset addressing.
// ---------------------------------------------------------------------------
__global__ __launch_bounds__(256, 4) void branch_kernel(
    const float* __restrict__ user_embs, const float* __restrict__ item_embs,
    const float* __restrict__ w_uu, const float* __restrict__ w_uiu,
    const float* __restrict__ w_uui,
    const int* __restrict__ uid, const int* __restrict__ nbr,
    const int* __restrict__ uiu, const int* __restrict__ uui, int B)
{
    __shared__ int   s_idx[2 * L];
    __shared__ float s_self[E];
    __shared__ __align__(16) float s_whi[E];
    __shared__ float s_red[8];
    __shared__ float s_S[8];
    __shared__ __align__(16) float s_acc[8][E];

    const int t    = threadIdx.x;
    const int wid  = t >> 5;
    const int lane = t & 31;
    const int b    = blockIdx.x;
    const int br   = blockIdx.y;
    const bool hasB = (br != 0);

    const float* tabA; const float* tabB; const float* w;
    const int* idx; int stride; float scale;
    if (br == 0)      { tabA = user_embs; tabB = user_embs; w = w_uu;  idx = nbr; stride = L;     scale = 0.5f;    }
    else if (br == 1) { tabA = item_embs; tabB = user_embs; w = w_uiu; idx = uiu; stride = 2 * L; scale = 1.f/3.f; }
    else              { tabA = user_embs; tabB = item_embs; w = w_uui; idx = uui; stride = 2 * L; scale = 1.f/3.f; }

    // Phase 0: warps 0-3 load indices; warps 4-7 load self/w + self-dots.
    if (t < stride) s_idx[t] = idx[(size_t)b * stride + t];
    if (t >= 128) {
        const int e = t - 128;
        const int u = uid[b];
        const float se  = user_embs[(size_t)u * E + e];
        const float wlo = w[e];
        const float whi = w[E + e];
        s_self[e] = se;
        s_whi[e]  = whi;
        const float p0 = warp_sum32(se * wlo);
        const float p1 = warp_sum32(se * whi);
        if (lane == 0) { s_red[wid - 4] = p0; s_red[4 + (wid - 4)] = p1; }
    }
    __syncthreads();

    const float c_lo = s_red[0] + s_red[1] + s_red[2] + s_red[3];
    const float c_hi = s_red[4] + s_red[5] + s_red[6] + s_red[7];
    const ulonglong2 wh2 = ((const ulonglong2*)s_whi)[lane];

    // Phase 1: load this warp's 8 rows (packed pairs) + dot partials.
    // 32-bit byte offsets (row*512B fits in 32 bits for both tables).
    int ia[8];
#pragma unroll
    for (int r = 0; r < 8; r++) ia[r] = s_idx[wid * 8 + r];

    const char* pa = (const char*)tabA;
    const char* pb = (const char*)tabB;
    const unsigned loff = (unsigned)lane << 4;

    ulonglong2 vs[8];
    float d[8];
#pragma unroll
    for (int r = 0; r < 8; r++) {
        const unsigned aoff = ((unsigned)ia[r] << 9) + loff;
        ulonglong2 va = *(const ulonglong2*)(pa + aoff);
        if (hasB) {
            const unsigned boff = ((unsigned)s_idx[L + wid * 8 + r] << 9) + loff;
            const ulonglong2 vb = *(const ulonglong2*)(pb + boff);
            va.x = add2(va.x, vb.x);
            va.y = add2(va.y, vb.y);
        }
        vs[r] = va;
        const ull d2 = fma2(va.y, wh2.y, mul2(va.x, wh2.x));
        const float2 dd = unpack2(d2);
        d[r] = dd.x + dd.y;
    }

    // Phase 2: pairing-tree reduction. Lane i ends with the FULL dot of
    // row r(i) = 4*bit2(i) + 2*bit3(i) + bit4(i).
    const bool b4 = lane & 16, b3 = lane & 8, b2 = lane & 4;
    float x4[4];
#pragma unroll
    for (int r = 0; r < 4; r++) {
        const float keep = b4 ? d[2 * r + 1] : d[2 * r];
        const float send = b4 ? d[2 * r]     : d[2 * r + 1];
        x4[r] = keep + __shfl_xor_sync(0xffffffffu, send, 16);
    }
    float z2[2];
#pragma unroll
    for (int r = 0; r < 2; r++) {
        const float keep = b3 ? x4[2 * r + 1] : x4[2 * r];
        const float send = b3 ? x4[2 * r]     : x4[2 * r + 1];
        z2[r] = keep + __shfl_xor_sync(0xffffffffu, send, 8);
    }
    float v = (b2 ? z2[1] : z2[0]) +
              __shfl_xor_sync(0xffffffffu, b2 ? z2[0] : z2[1], 4);
    v += __shfl_xor_sync(0xffffffffu, v, 2);
    v += __shfl_xor_sync(0xffffffffu, v, 1);

    // Phase 3: one logit + exp per lane; masked rows -> exact 0 weight.
    const int myrow = (b2 ? 4 : 0) + (b3 ? 2 : 0) + (b4 ? 1 : 0);
    const int myidx = ia[myrow];
    float xl = c_lo + scale * (c_hi + v);
    xl = (xl > 0.f) ? xl : 0.01f * xl;              // leaky_relu
    const float e_mine = (myidx == 0) ? 0.f : __expf(xl);

    // Broadcast: row r lives in lane src(r) = ((r&1)<<4)|((r&2)<<2)|(r&4).
    float S = 0.f;
    ulonglong2 acc; acc.x = 0ull; acc.y = 0ull;
#pragma unroll
    for (int r = 0; r < 8; r++) {
        const int src = ((r & 1) << 4) | ((r & 2) << 2) | (r & 4);
        const float e = __shfl_sync(0xffffffffu, e_mine, src);
        S += e;
        const ull e2 = pack2(e, e);
        acc.x = fma2(e2, vs[r].x, acc.x);
        acc.y = fma2(e2, vs[r].y, acc.y);
    }

    ((ulonglong2*)s_acc[wid])[lane] = acc;
    if (lane == 0) s_S[wid] = S;
    __syncthreads();

    // Phase 4: plain cross-warp sum + store (threads 0..127).
    if (t < E) {
        const float T = s_S[0] + s_S[1] + s_S[2] + s_S[3] +
                        s_S[4] + s_S[5] + s_S[6] + s_S[7];
        const float val = s_acc[0][t] + s_acc[1][t] + s_acc[2][t] + s_acc[3][t] +
                          s_acc[4][t] + s_acc[5][t] + s_acc[6][t] + s_acc[7][t];
        const float f = scale * (s_self[t] + val / T);
        g_feats[((size_t)br * B + b) * E + t] = fmaxf(f, 0.f);
    }
}

// ---------------------------------------------------------------------------
// Scores: per-block partial of sum_b tanh(feat_b @ W0 + b0) . w1
// f32x2 over the E dimension: W0 transposed in smem (pad 130, conflict-free),
// 4 LDS.64 + 4 FMA2 per 2 e-steps (was 8 LDS + 8 FMA).
// ---------------------------------------------------------------------------
__global__ __launch_bounds__(256) void scores_kernel(
    const float* __restrict__ W0, const float* __restrict__ b0,
    const float* __restrict__ w1, int B)
{
    __shared__ __align__(8) float sW0t[64 * W0PAD];   // [col][e], padded
    __shared__ float sb0[64];
    __shared__ float sw1[64];
    __shared__ __align__(8) float sfeat[SROWS][E];
    __shared__ float s_part[8];

    const int t = threadIdx.x;
    const int wid = t >> 5, lane = t & 31;

    const int br = blockIdx.y;
    const int base = blockIdx.x * SROWS;
    const float* fp = g_feats + ((size_t)br * B + base) * E;

#pragma unroll
    for (int r = 0; r < 4; r++) {
        const int row = wid * 4 + r;
        ((float4*)sfeat[row])[lane] = ((const float4*)(fp + (size_t)row * E))[lane];
    }
    // Transposed W0: sW0t[col*W0PAD + e] = W0[e*64 + col]
    for (int i = t; i < E * 64; i += 256) {
        const int e = i >> 6, col = i & 63;
        sW0t[col * W0PAD + e] = W0[i];
    }
    if (t < 64) { sb0[t] = b0[t]; sw1[t] = w1[t]; }
    __syncthreads();

    const int cA = lane, cB = lane + 32;
    float warp_sum = 0.f;
#pragma unroll
    for (int p = 0; p < 2; p++) {
        const int r0 = wid * 4 + p * 2;
        ull a00 = 0, a01 = 0, a10 = 0, a11 = 0;
#pragma unroll
        for (int e = 0; e < E; e += 2) {
            const ull f0 = *(const ull*)&sfeat[r0][e];
            const ull f1 = *(const ull*)&sfeat[r0 + 1][e];
            const ull wA = *(const ull*)&sW0t[cA * W0PAD + e];
            const ull wB = *(const ull*)&sW0t[cB * W0PAD + e];
            a00 = fma2(f0, wA, a00); a01 = fma2(f0, wB, a01);
            a10 = fma2(f1, wA, a10); a11 = fma2(f1, wB, a11);
        }
        const float2 u00 = unpack2(a00), u01 = unpack2(a01);
        const float2 u10 = unpack2(a10), u11 = unpack2(a11);
        const float d00 = u00.x + u00.y + sb0[cA];
        const float d01 = u01.x + u01.y + sb0[cB];
        const float d10 = u10.x + u10.y + sb0[cA];
        const float d11 = u11.x + u11.y + sb0[cB];
        warp_sum += (tanhf(d00) + tanhf(d10)) * sw1[cA] +
                    (tanhf(d01) + tanhf(d11)) * sw1[cB];
    }
    warp_sum = warp_sum32(warp_sum);
    if (lane == 0) s_part[wid] = warp_sum;
    __syncthreads();
    if (t == 0) {
        g_part[br * MAX_PARTS + blockIdx.x] =
            s_part[0] + s_part[1] + s_part[2] + s_part[3] +
            s_part[4] + s_part[5] + s_part[6] + s_part[7];
    }
}

// ---------------------------------------------------------------------------
// Mix (R11 config): gathers first, gate reduction overlapped, then combine.
// ---------------------------------------------------------------------------
__global__ __launch_bounds__(256) void mix_kernel(
    float4* __restrict__ out, int B, int nparts)
{
    __shared__ float ssc[3];
    const int t = threadIdx.x, wid = t >> 5, lane = t & 31;

    const int i = blockIdx.x * blockDim.x + t;
    const int total = B * E / 4;
    const bool valid = (i < total);

    float4 a, b4v, c;
    if (valid) {
        a   = ((const float4*)g_feats)[i];
        b4v = ((const float4*)(g_feats + (size_t)B * E))[i];
        c   = ((const float4*)(g_feats + (size_t)2 * B * E))[i];
    }

    if (wid < 3) {
        float v = 0.f;
        if ((nparts & 3) == 0) {
            const float4* gp = (const float4*)(g_part + wid * MAX_PARTS);
            for (int j = lane; j * 4 < nparts; j += 32) {
                const float4 p = gp[j];
                v += (p.x + p.y) + (p.z + p.w);
            }
        } else {
            for (int j = lane; j < nparts; j += 32)
                v += g_part[wid * MAX_PARTS + j];
        }
        v = warp_sum32(v);
        if (lane == 0) ssc[wid] = v;
    }
    __syncthreads();

    const float inv = 1.f / (float)B;
    const float s0 = ssc[0] * inv, s1 = ssc[1] * inv, s2 = ssc[2] * inv;
    const float m = fmaxf(s0, fmaxf(s1, s2));
    const float e0 = expf(s0 - m), e1 = expf(s1 - m), e2 = expf(s2 - m);
    const float dd = 1.f / (e0 + e1 + e2);

    if (!valid) return;
    float4 r;
    r.x = fmaxf((e0 * a.x + e1 * b4v.x + e2 * c.x) * dd, 0.f);
    r.y = fmaxf((e0 * a.y + e1 * b4v.y + e2 * c.y) * dd, 0.f);
    r.z = fmaxf((e0 * a.z + e1 * b4v.z + e2 * c.z) * dd, 0.f);
    r.w = fmaxf((e0 * a.w + e1 * b4v.w + e2 * c.w) * dd, 0.f);
    out[i] = r;
}

extern "C" void kernel_launch(void* const* d_in, const int* in_sizes, int n_in,
                              void* d_out, int out_size) {
    const float* user_embs = (const float*)d_in[0];
    const float* item_embs = (const float*)d_in[1];
    const float* w_uu  = (const float*)d_in[2];
    const float* w_uiu = (const float*)d_in[3];
    const float* w_uui = (const float*)d_in[4];
    const float* W0 = (const float*)d_in[5];
    const float* b0 = (const float*)d_in[6];
    const float* w1 = (const float*)d_in[7];
    const int* uid = (const int*)d_in[8];
    const int* nbr = (const int*)d_in[9];
    const int* uiu = (const int*)d_in[10];
    const int* uui = (const int*)d_in[11];
    float* out = (float*)d_out;

    const int B = in_sizes[8];

    branch_kernel<<<dim3(B, 3), 256>>>(user_embs, item_embs, w_uu, w_uiu, w_uui,
                                       uid, nbr, uiu, uui, B);

    const int nparts = B / SROWS;
    dim3 g2(nparts, 3);
    scores_kernel<<<g2, 256>>>(W0, b0, w1, B);

    const int total4 = B * E / 4;
    mix_kernel<<<(total4 + 255) / 256, 256>>>((float4*)out, B, nparts);
}

// round 16
// speedup vs baseline: 1.1046x; 1.1046x over previous
#include <cuda_runtime.h>
#include <cstdint>

#define E 128
#define L 64
#define MAX_B 8192
#define SROWS 32
#define MAX_PARTS (MAX_B / SROWS)
#define W0PAD 130

typedef unsigned long long ull;

__device__ __align__(16) float g_feats[3ull * MAX_B * E];
__device__ __align__(16) float g_part[3 * MAX_PARTS];

__device__ __forceinline__ float warp_sum32(float v) {
#pragma unroll
    for (int o = 16; o > 0; o >>= 1) v += __shfl_xor_sync(0xffffffffu, v, o);
    return v;
}

// ---- Blackwell packed f32x2 ops (SASS FFMA2/FADD2, PTX-only) ----
__device__ __forceinline__ ull fma2(ull a, ull b, ull c) {
    ull r; asm("fma.rn.f32x2 %0, %1, %2, %3;" : "=l"(r) : "l"(a), "l"(b), "l"(c));
    return r;
}
__device__ __forceinline__ ull add2(ull a, ull b) {
    ull r; asm("add.rn.f32x2 %0, %1, %2;" : "=l"(r) : "l"(a), "l"(b));
    return r;
}
__device__ __forceinline__ ull mul2(ull a, ull b) {
    ull r; asm("mul.rn.f32x2 %0, %1, %2;" : "=l"(r) : "l"(a), "l"(b));
    return r;
}
__device__ __forceinline__ float2 unpack2(ull v) {
    float2 f; asm("mov.b64 {%0, %1}, %2;" : "=f"(f.x), "=f"(f.y) : "l"(v));
    return f;
}
__device__ __forceinline__ ull pack2(float a, float b) {
    ull r; asm("mov.b64 %0, {%1, %2};" : "=l"(r) : "f"(a), "f"(b));
    return r;
}

// ---------------------------------------------------------------------------
// Fused branch kernel — EXACT R11 configuration (best measured: 62.2 us).
// grid (B, 3), 256 threads, 8 rows/warp, packed f32x2 math, pairing tree,
// one exp per lane, unstabilized softmax with exact-0 masked weights.
// ---------------------------------------------------------------------------
__global__ __launch_bounds__(256, 4) void branch_kernel(
    const float* __restrict__ user_embs, const float* __restrict__ item_embs,
    const float* __restrict__ w_uu, const float* __restrict__ w_uiu,
    const float* __restrict__ w_uui,
    const int* __restrict__ uid, const int* __restrict__ nbr,
    const int* __restrict__ uiu, const int* __restrict__ uui, int B)
{
    __shared__ int   s_idx[2 * L];
    __shared__ float s_self[E];
    __shared__ __align__(16) float s_whi[E];
    __shared__ float s_red[8];
    __shared__ float s_S[8];
    __shared__ __align__(16) float s_acc[8][E];

    const int t    = threadIdx.x;
    const int wid  = t >> 5;
    const int lane = t & 31;
    const int b    = blockIdx.x;
    const int br   = blockIdx.y;
    const bool hasB = (br != 0);

    const float* tabA; const float* tabB; const float* w;
    const int* idx; int stride; float scale;
    if (br == 0)      { tabA = user_embs; tabB = user_embs; w = w_uu;  idx = nbr; stride = L;     scale = 0.5f;    }
    else if (br == 1) { tabA = item_embs; tabB = user_embs; w = w_uiu; idx = uiu; stride = 2 * L; scale = 1.f/3.f; }
    else              { tabA = user_embs; tabB = item_embs; w = w_uui; idx = uui; stride = 2 * L; scale = 1.f/3.f; }

    // Phase 0: warps 0-3 load indices; warps 4-7 load self/w + self-dots.
    if (t < stride) s_idx[t] = idx[(size_t)b * stride + t];
    if (t >= 128) {
        const int e = t - 128;
        const int u = uid[b];
        const float se  = user_embs[(size_t)u * E + e];
        const float wlo = w[e];
        const float whi = w[E + e];
        s_self[e] = se;
        s_whi[e]  = whi;
        const float p0 = warp_sum32(se * wlo);
        const float p1 = warp_sum32(se * whi);
        if (lane == 0) { s_red[wid - 4] = p0; s_red[4 + (wid - 4)] = p1; }
    }
    __syncthreads();

    const float c_lo = s_red[0] + s_red[1] + s_red[2] + s_red[3];
    const float c_hi = s_red[4] + s_red[5] + s_red[6] + s_red[7];
    const ulonglong2 wh2 = ((const ulonglong2*)s_whi)[lane];

    // Phase 1: load this warp's 8 rows (packed pairs) + dot partials.
    int ia[8];
#pragma unroll
    for (int r = 0; r < 8; r++) ia[r] = s_idx[wid * 8 + r];

    ulonglong2 vs[8];
    float d[8];
#pragma unroll
    for (int r = 0; r < 8; r++) {
        ulonglong2 va = ((const ulonglong2*)(tabA + (size_t)ia[r] * E))[lane];
        if (hasB) {
            const int ib = s_idx[L + wid * 8 + r];
            const ulonglong2 vb = ((const ulonglong2*)(tabB + (size_t)ib * E))[lane];
            va.x = add2(va.x, vb.x);
            va.y = add2(va.y, vb.y);
        }
        vs[r] = va;
        const ull d2 = fma2(va.y, wh2.y, mul2(va.x, wh2.x));
        const float2 dd = unpack2(d2);
        d[r] = dd.x + dd.y;
    }

    // Phase 2: pairing-tree reduction. Lane i ends with the FULL dot of
    // row r(i) = 4*bit2(i) + 2*bit3(i) + bit4(i).
    const bool b4 = lane & 16, b3 = lane & 8, b2 = lane & 4;
    float x4[4];
#pragma unroll
    for (int r = 0; r < 4; r++) {
        const float keep = b4 ? d[2 * r + 1] : d[2 * r];
        const float send = b4 ? d[2 * r]     : d[2 * r + 1];
        x4[r] = keep + __shfl_xor_sync(0xffffffffu, send, 16);
    }
    float z2[2];
#pragma unroll
    for (int r = 0; r < 2; r++) {
        const float keep = b3 ? x4[2 * r + 1] : x4[2 * r];
        const float send = b3 ? x4[2 * r]     : x4[2 * r + 1];
        z2[r] = keep + __shfl_xor_sync(0xffffffffu, send, 8);
    }
    float v = (b2 ? z2[1] : z2[0]) +
              __shfl_xor_sync(0xffffffffu, b2 ? z2[0] : z2[1], 4);
    v += __shfl_xor_sync(0xffffffffu, v, 2);
    v += __shfl_xor_sync(0xffffffffu, v, 1);

    // Phase 3: one logit + exp per lane; masked rows -> exact 0 weight.
    const int myrow = (b2 ? 4 : 0) + (b3 ? 2 : 0) + (b4 ? 1 : 0);
    const int myidx = s_idx[wid * 8 + myrow];
    float xl = c_lo + scale * (c_hi + v);
    xl = (xl > 0.f) ? xl : 0.01f * xl;              // leaky_relu
    const float e_mine = (myidx == 0) ? 0.f : __expf(xl);

    // Broadcast: row r lives in lane src(r) = ((r&1)<<4)|((r&2)<<2)|(r&4).
    float S = 0.f;
    ulonglong2 acc; acc.x = 0ull; acc.y = 0ull;
#pragma unroll
    for (int r = 0; r < 8; r++) {
        const int src = ((r & 1) << 4) | ((r & 2) << 2) | (r & 4);
        const float e = __shfl_sync(0xffffffffu, e_mine, src);
        S += e;
        const ull e2 = pack2(e, e);
        acc.x = fma2(e2, vs[r].x, acc.x);
        acc.y = fma2(e2, vs[r].y, acc.y);
    }

    ((ulonglong2*)s_acc[wid])[lane] = acc;
    if (lane == 0) s_S[wid] = S;
    __syncthreads();

    // Phase 4: plain cross-warp sum + store (threads 0..127).
    if (t < E) {
        const float T = s_S[0] + s_S[1] + s_S[2] + s_S[3] +
                        s_S[4] + s_S[5] + s_S[6] + s_S[7];
        const float val = s_acc[0][t] + s_acc[1][t] + s_acc[2][t] + s_acc[3][t] +
                          s_acc[4][t] + s_acc[5][t] + s_acc[6][t] + s_acc[7][t];
        const float f = scale * (s_self[t] + val / T);
        g_feats[((size_t)br * B + b) * E + t] = fmaxf(f, 0.f);
    }
}

// ---------------------------------------------------------------------------
// Scores: per-block partial of sum_b tanh(feat_b @ W0 + b0) . w1
// f32x2 over the E dimension: W0 transposed in smem (pad 130, conflict-free),
// 4 LDS.64 + 4 FMA2 per 2 e-steps (was 8 LDS + 8 FMA).
// ---------------------------------------------------------------------------
__global__ __launch_bounds__(256) void scores_kernel(
    const float* __restrict__ W0, const float* __restrict__ b0,
    const float* __restrict__ w1, int B)
{
    __shared__ __align__(8) float sW0t[64 * W0PAD];   // [col][e], padded
    __shared__ float sb0[64];
    __shared__ float sw1[64];
    __shared__ __align__(8) float sfeat[SROWS][E];
    __shared__ float s_part[8];

    const int t = threadIdx.x;
    const int wid = t >> 5, lane = t & 31;

    const int br = blockIdx.y;
    const int base = blockIdx.x * SROWS;
    const float* fp = g_feats + ((size_t)br * B + base) * E;

#pragma unroll
    for (int r = 0; r < 4; r++) {
        const int row = wid * 4 + r;
        ((float4*)sfeat[row])[lane] = ((const float4*)(fp + (size_t)row * E))[lane];
    }
    // Transposed W0: sW0t[col*W0PAD + e] = W0[e*64 + col]
    for (int i = t; i < E * 64; i += 256) {
        const int e = i >> 6, col = i & 63;
        sW0t[col * W0PAD + e] = W0[i];
    }
    if (t < 64) { sb0[t] = b0[t]; sw1[t] = w1[t]; }
    __syncthreads();

    const int cA = lane, cB = lane + 32;
    float warp_sum = 0.f;
#pragma unroll
    for (int p = 0; p < 2; p++) {
        const int r0 = wid * 4 + p * 2;
        ull a00 = 0, a01 = 0, a10 = 0, a11 = 0;
#pragma unroll
        for (int e = 0; e < E; e += 2) {
            const ull f0 = *(const ull*)&sfeat[r0][e];
            const ull f1 = *(const ull*)&sfeat[r0 + 1][e];
            const ull wA = *(const ull*)&sW0t[cA * W0PAD + e];
            const ull wB = *(const ull*)&sW0t[cB * W0PAD + e];
            a00 = fma2(f0, wA, a00); a01 = fma2(f0, wB, a01);
            a10 = fma2(f1, wA, a10); a11 = fma2(f1, wB, a11);
        }
        const float2 u00 = unpack2(a00), u01 = unpack2(a01);
        const float2 u10 = unpack2(a10), u11 = unpack2(a11);
        const float d00 = u00.x + u00.y + sb0[cA];
        const float d01 = u01.x + u01.y + sb0[cB];
        const float d10 = u10.x + u10.y + sb0[cA];
        const float d11 = u11.x + u11.y + sb0[cB];
        warp_sum += (tanhf(d00) + tanhf(d10)) * sw1[cA] +
                    (tanhf(d01) + tanhf(d11)) * sw1[cB];
    }
    warp_sum = warp_sum32(warp_sum);
    if (lane == 0) s_part[wid] = warp_sum;
    __syncthreads();
    if (t == 0) {
        g_part[br * MAX_PARTS + blockIdx.x] =
            s_part[0] + s_part[1] + s_part[2] + s_part[3] +
            s_part[4] + s_part[5] + s_part[6] + s_part[7];
    }
}

// ---------------------------------------------------------------------------
// Mix (R11 config): gathers first, gate reduction overlapped, then combine.
// ---------------------------------------------------------------------------
__global__ __launch_bounds__(256) void mix_kernel(
    float4* __restrict__ out, int B, int nparts)
{
    __shared__ float ssc[3];
    const int t = threadIdx.x, wid = t >> 5, lane = t & 31;

    const int i = blockIdx.x * blockDim.x + t;
    const int total = B * E / 4;
    const bool valid = (i < total);

    float4 a, b4v, c;
    if (valid) {
        a   = ((const float4*)g_feats)[i];
        b4v = ((const float4*)(g_feats + (size_t)B * E))[i];
        c   = ((const float4*)(g_feats + (size_t)2 * B * E))[i];
    }

    if (wid < 3) {
        float v = 0.f;
        if ((nparts & 3) == 0) {
            const float4* gp = (const float4*)(g_part + wid * MAX_PARTS);
            for (int j = lane; j * 4 < nparts; j += 32) {
                const float4 p = gp[j];
                v += (p.x + p.y) + (p.z + p.w);
            }
        } else {
            for (int j = lane; j < nparts; j += 32)
                v += g_part[wid * MAX_PARTS + j];
        }
        v = warp_sum32(v);
        if (lane == 0) ssc[wid] = v;
    }
    __syncthreads();

    const float inv = 1.f / (float)B;
    const float s0 = ssc[0] * inv, s1 = ssc[1] * inv, s2 = ssc[2] * inv;
    const float m = fmaxf(s0, fmaxf(s1, s2));
    const float e0 = expf(s0 - m), e1 = expf(s1 - m), e2 = expf(s2 - m);
    const float dd = 1.f / (e0 + e1 + e2);

    if (!valid) return;
    float4 r;
    r.x = fmaxf((e0 * a.x + e1 * b4v.x + e2 * c.x) * dd, 0.f);
    r.y = fmaxf((e0 * a.y + e1 * b4v.y + e2 * c.y) * dd, 0.f);
    r.z = fmaxf((e0 * a.z + e1 * b4v.z + e2 * c.z) * dd, 0.f);
    r.w = fmaxf((e0 * a.w + e1 * b4v.w + e2 * c.w) * dd, 0.f);
    out[i] = r;
}

extern "C" void kernel_launch(void* const* d_in, const int* in_sizes, int n_in,
                              void* d_out, int out_size) {
    const float* user_embs = (const float*)d_in[0];
    const float* item_embs = (const float*)d_in[1];
    const float* w_uu  = (const float*)d_in[2];
    const float* w_uiu = (const float*)d_in[3];
    const float* w_uui = (const float*)d_in[4];
    const float* W0 = (const float*)d_in[5];
    const float* b0 = (const float*)d_in[6];
    const float* w1 = (const float*)d_in[7];
    const int* uid = (const int*)d_in[8];
    const int* nbr = (const int*)d_in[9];
    const int* uiu = (const int*)d_in[10];
    const int* uui = (const int*)d_in[11];
    float* out = (float*)d_out;

    const int B = in_sizes[8];

    branch_kernel<<<dim3(B, 3), 256>>>(user_embs, item_embs, w_uu, w_uiu, w_uui,
                                       uid, nbr, uiu, uui, B);

    const int nparts = B / SROWS;
    dim3 g2(nparts, 3);
    scores_kernel<<<g2, 256>>>(W0, b0, w1, B);

    const int total4 = B * E / 4;
    mix_kernel<<<(total4 + 255) / 256, 256>>>((float4*)out, B, nparts);
}